// round 7
// baseline (speedup 1.0000x reference)
#include <cuda_runtime.h>

#define NN 50000
#define EE 800000
#define EMBD 64
#define LL 4
#define BN_EPS 1e-5f
#define GROUP 512
#define NG ((NN + GROUP - 1) / GROUP)   // 98

// ---------------- scratch (device globals; no allocation allowed) ----------
__device__ __align__(256) float g_bufA[NN * EMBD];   // agg output / t2
__device__ __align__(256) float g_bufB[NN * EMBD];   // t (gemm1 out)
__device__ int   g_off[NN + 1];
__device__ int   g_cur[NN];
__device__ int2  g_edge[EE];            // packed (src, weight-bits)
__device__ int   g_part[NG];
__device__ float g_sumL[8][64];         // per-BN stat slots (4 layers x {inner,outer})
__device__ float g_sqL[8][64];

// ---------------- init: zero counters + all stat slots ---------------------
__global__ void k_init() {
    int i = blockIdx.x * blockDim.x + threadIdx.x;
    if (i < NN) g_cur[i] = 0;
    if (i < 8 * 64) { (&g_sumL[0][0])[i] = 0.f; (&g_sqL[0][0])[i] = 0.f; }
}

__global__ void k_hist(const int* __restrict__ ei) {
    int e = blockIdx.x * blockDim.x + threadIdx.x;
    if (e < EE) atomicAdd(&g_cur[ei[EE + e]], 1);
}

// ---------------- 3-phase exclusive scan over g_cur -> g_off ---------------
__global__ void k_scanA() {
    __shared__ int s_warp[32];
    int tid = threadIdx.x, lane = tid & 31, wid = tid >> 5;
    int i = blockIdx.x * GROUP + tid;
    int d = (i < NN) ? g_cur[i] : 0;
    int v = d;
    #pragma unroll
    for (int o = 1; o < 32; o <<= 1) {
        int t = __shfl_up_sync(0xffffffffu, v, o);
        if (lane >= o) v += t;
    }
    if (lane == 31) s_warp[wid] = v;
    __syncthreads();
    if (wid == 0) {
        int w = (lane < 16) ? s_warp[lane] : 0;
        #pragma unroll
        for (int o = 1; o < 32; o <<= 1) {
            int t = __shfl_up_sync(0xffffffffu, w, o);
            if (lane >= o) w += t;
        }
        if (lane < 16) s_warp[lane] = w;
    }
    __syncthreads();
    int excl = (wid ? s_warp[wid - 1] : 0) + v - d;
    if (i < NN) g_off[i] = excl;
    if (tid == 0) g_part[blockIdx.x] = s_warp[15];   // block total
}

// parallel scan over NG (=98) partials, one 128-thread block
__global__ void k_scanB() {
    __shared__ int wtot[4];
    int tid = threadIdx.x, lane = tid & 31, wid = tid >> 5;
    int d = (tid < NG) ? g_part[tid] : 0;
    int v = d;
    #pragma unroll
    for (int o = 1; o < 32; o <<= 1) {
        int t = __shfl_up_sync(0xffffffffu, v, o);
        if (lane >= o) v += t;
    }
    if (lane == 31) wtot[wid] = v;
    __syncthreads();
    int add = 0;
    #pragma unroll
    for (int w = 0; w < 4; w++) add += (w < wid) ? wtot[w] : 0;
    if (tid < NG) g_part[tid] = add + v - d;
}

__global__ void k_scanC() {
    int i = blockIdx.x * GROUP + threadIdx.x;
    if (i < NN) {
        int o = g_off[i] + g_part[blockIdx.x];
        g_off[i] = o;
        g_cur[i] = o;
    }
    if (i == 0) g_off[NN] = EE;
}

__global__ void k_fill(const int* __restrict__ ei, const float* __restrict__ ew) {
    int e = blockIdx.x * blockDim.x + threadIdx.x;
    if (e < EE) {
        int d = ei[EE + e];
        int p = atomicAdd(&g_cur[d], 1);
        g_edge[p] = make_int2(ei[e], __float_as_int(ew[e]));
    }
}

// ---------------- aggregation: warp per node, no atomics, MLP=4 ------------
__global__ void k_agg(const float* __restrict__ h) {
    int gw   = (blockIdx.x * blockDim.x + threadIdx.x) >> 5;
    int lane = threadIdx.x & 31;
    if (gw >= NN) return;
    int beg = g_off[gw], end = g_off[gw + 1];
    const float2* __restrict__ h2 = (const float2*)h;
    float2 acc = h2[gw * 32 + lane];            // self term: agg + h
    int i = beg;
    for (; i + 4 <= end; i += 4) {
        int2 e0 = __ldg(&g_edge[i]);
        int2 e1 = __ldg(&g_edge[i + 1]);
        int2 e2 = __ldg(&g_edge[i + 2]);
        int2 e3 = __ldg(&g_edge[i + 3]);
        float2 v0 = h2[e0.x * 32 + lane];
        float2 v1 = h2[e1.x * 32 + lane];
        float2 v2 = h2[e2.x * 32 + lane];
        float2 v3 = h2[e3.x * 32 + lane];
        float w0 = __int_as_float(e0.y), w1 = __int_as_float(e1.y);
        float w2 = __int_as_float(e2.y), w3 = __int_as_float(e3.y);
        acc.x = fmaf(w0, v0.x, acc.x);  acc.y = fmaf(w0, v0.y, acc.y);
        acc.x = fmaf(w1, v1.x, acc.x);  acc.y = fmaf(w1, v1.y, acc.y);
        acc.x = fmaf(w2, v2.x, acc.x);  acc.y = fmaf(w2, v2.y, acc.y);
        acc.x = fmaf(w3, v3.x, acc.x);  acc.y = fmaf(w3, v3.y, acc.y);
    }
    for (; i < end; i++) {
        int2 e0 = __ldg(&g_edge[i]);
        float2 v0 = h2[e0.x * 32 + lane];
        float w0 = __int_as_float(e0.y);
        acc.x = fmaf(w0, v0.x, acc.x);
        acc.y = fmaf(w0, v0.y, acc.y);
    }
    ((float2*)g_bufA)[gw * 32 + lane] = acc;
}

// ------- 64x64 GEMM: 512 thr = 128 rows x 4 N-quarters, f32x2, dbl-buf -----
// STATS: accumulate per-feature sum & sumsq of Y into slotOut
// TRANS: x -> relu(x*scale + shift), scale/shift from slotIn stats + gamma/beta
// SRC/DST: 0 = use pointer arg, 1 = g_bufA, 2 = g_bufB
template <int STATS, int TRANS, int SRC, int DST>
__global__ void __launch_bounds__(512, 2) k_gemm(
    const float* __restrict__ Xarg, const float* __restrict__ W,
    const float* __restrict__ bias, float* __restrict__ Yarg,
    const float* __restrict__ gma, const float* __restrict__ bta,
    int slotIn, int slotOut, int n)
{
    const float* X = (SRC == 1) ? g_bufA : (SRC == 2) ? g_bufB : Xarg;
    float*       Y = (DST == 1) ? g_bufA : (DST == 2) ? g_bufB : Yarg;

    __shared__ float4 Ws[64 * 16];      // 16 KB, row k: 64 output features
    __shared__ float  Xs[2][128 * 17];  // 17.4 KB, double-buffered k-quarters
    __shared__ float  Bs[64];
    __shared__ float  Ss[64];
    __shared__ float  Hs[64];
    __shared__ float  Rs[16 * 32];      // 2 KB: per-warp 16 sums + 16 sqs

    int tid  = threadIdx.x;
    int nq   = tid >> 7;                // output quarter 0..3 (constant per warp)
    int row  = tid & 127;               // row within block
    int base = blockIdx.x * 128;
    bool valid = (base + row) < n;

    for (int i = tid; i < 64 * 16; i += 512) Ws[i] = ((const float4*)W)[i];
    if (tid < 64) {
        Bs[tid] = bias[tid];
        if (TRANS) {
            float mean = g_sumL[slotIn][tid] * (1.f / NN);
            float var  = g_sqL[slotIn][tid] * (1.f / NN) - mean * mean;
            float rs   = rsqrtf(var + BN_EPS);
            float sc   = rs * gma[tid];
            Ss[tid] = sc;
            Hs[tid] = bta[tid] - mean * sc;
        }
    }

    // quarter staging: 128 rows x 16 k = 512 float4; ONE float4 per thread
    int prow = tid >> 2, pc4 = tid & 3;
    float4 pre;
    auto loadQ = [&](int q) {
        pre = make_float4(0.f, 0.f, 0.f, 0.f);
        if (base + prow < n)
            pre = ((const float4*)X)[(base + prow) * 16 + q * 4 + pc4];
    };
    auto storeQ = [&](int b) {
        float* p = &Xs[b][prow * 17 + pc4 * 4];
        p[0] = pre.x; p[1] = pre.y; p[2] = pre.z; p[3] = pre.w;
    };

    // 8 packed f32x2 accumulators = 16 fp32 outputs (this thread's quarter)
    unsigned long long acc2[8];
    #pragma unroll
    for (int j = 0; j < 8; j++) acc2[j] = 0ull;

    loadQ(0);
    storeQ(0);
    __syncthreads();

    #pragma unroll
    for (int q = 0; q < 4; q++) {
        if (q < 3) loadQ(q + 1);                  // LDG in flight during compute
        const float* xr = &Xs[q & 1][row * 17];
        #pragma unroll
        for (int k = 0; k < 16; k++) {
            float xk = xr[k];
            int   kk = q * 16 + k;
            if (TRANS) xk = fmaxf(fmaf(xk, Ss[kk], Hs[kk]), 0.f);
            unsigned long long xk2;
            unsigned int xi = __float_as_uint(xk);
            asm("mov.b64 %0, {%1, %1};" : "=l"(xk2) : "r"(xi));
            const ulonglong2* wrow = (const ulonglong2*)&Ws[kk * 16 + nq * 4];
            #pragma unroll
            for (int j = 0; j < 4; j++) {
                ulonglong2 w2 = wrow[j];          // one LDS.128 (warp broadcast)
                asm("fma.rn.f32x2 %0, %1, %2, %0;" : "+l"(acc2[2 * j])     : "l"(xk2), "l"(w2.x));
                asm("fma.rn.f32x2 %0, %1, %2, %0;" : "+l"(acc2[2 * j + 1]) : "l"(xk2), "l"(w2.y));
            }
        }
        if (q < 3) {
            storeQ((q + 1) & 1);                  // other buffer: safe pre-sync
            __syncthreads();
        }
    }

    // unpack to 4 float4 (cols nq*16 + 4j + 0..3)
    float4 acc[4];
    #pragma unroll
    for (int j = 0; j < 4; j++) {
        uint2 lo = *(uint2*)&acc2[2 * j];
        uint2 hi = *(uint2*)&acc2[2 * j + 1];
        acc[j].x = __uint_as_float(lo.x);
        acc[j].y = __uint_as_float(lo.y);
        acc[j].z = __uint_as_float(hi.x);
        acc[j].w = __uint_as_float(hi.y);
    }

    if (valid) {
        #pragma unroll
        for (int j = 0; j < 4; j++) {
            acc[j].x += Bs[nq * 16 + j * 4 + 0];
            acc[j].y += Bs[nq * 16 + j * 4 + 1];
            acc[j].z += Bs[nq * 16 + j * 4 + 2];
            acc[j].w += Bs[nq * 16 + j * 4 + 3];
            ((float4*)Y)[(base + row) * 16 + nq * 4 + j] = acc[j];
        }
    } else {
        // phantom tail rows must contribute zeros to BN stats
        #pragma unroll
        for (int j = 0; j < 4; j++) acc[j] = make_float4(0.f, 0.f, 0.f, 0.f);
    }

    if (STATS) {
        int lane = tid & 31, wid = tid >> 5;      // 16 warps; warp covers quarter wid>>2
        #pragma unroll
        for (int j = 0; j < 4; j++) {
            float vv[4] = { acc[j].x, acc[j].y, acc[j].z, acc[j].w };
            #pragma unroll
            for (int c = 0; c < 4; c++) {
                float s = vv[c];
                float q = s * s;
                #pragma unroll
                for (int o = 16; o > 0; o >>= 1) {
                    s += __shfl_down_sync(0xffffffffu, s, o);
                    q += __shfl_down_sync(0xffffffffu, q, o);
                }
                if (lane == 0) {
                    Rs[wid * 32 + j * 4 + c]      = s;   // col j*4+c of quarter
                    Rs[wid * 32 + 16 + j * 4 + c] = q;
                }
            }
        }
        __syncthreads();
        if (tid < 128) {
            int f = tid & 63, w = tid >> 6;       // w=0: sum, w=1: sq
            int nf = f >> 4, col = f & 15;
            int b0 = (nf * 4) * 32 + w * 16 + col;
            float t = Rs[b0] + Rs[b0 + 32] + Rs[b0 + 64] + Rs[b0 + 96];
            atomicAdd(w ? &g_sqL[slotOut][f] : &g_sumL[slotOut][f], t);
        }
    }
}

// ---------------- outer BN apply + ReLU + residual (t2 = g_bufA) -----------
__global__ void __launch_bounds__(256) k_resid(
    float* __restrict__ h, const float* __restrict__ gma,
    const float* __restrict__ bta, int slot)
{
    __shared__ float Ss[64];
    __shared__ float Hs[64];
    int tid = threadIdx.x;
    if (tid < 64) {
        float mean = g_sumL[slot][tid] * (1.f / NN);
        float var  = g_sqL[slot][tid] * (1.f / NN) - mean * mean;
        float rs   = rsqrtf(var + BN_EPS);
        float sc   = rs * gma[tid];
        Ss[tid] = sc;
        Hs[tid] = bta[tid] - mean * sc;
    }
    __syncthreads();
    int i = blockIdx.x * blockDim.x + tid;
    if (i < NN * EMBD / 4) {
        int fb = (i & 15) * 4;
        float4 v  = ((const float4*)g_bufA)[i];
        float4 hh = ((const float4*)h)[i];
        v.x = fmaxf(fmaf(v.x, Ss[fb + 0], Hs[fb + 0]), 0.f) + hh.x;
        v.y = fmaxf(fmaf(v.y, Ss[fb + 1], Hs[fb + 1]), 0.f) + hh.y;
        v.z = fmaxf(fmaf(v.z, Ss[fb + 2], Hs[fb + 2]), 0.f) + hh.z;
        v.w = fmaxf(fmaf(v.w, Ss[fb + 3], Hs[fb + 3]), 0.f) + hh.w;
        ((float4*)h)[i] = v;
    }
}

// ---------------- launch ----------------------------------------------------
extern "C" void kernel_launch(void* const* d_in, const int* in_sizes, int n_in,
                              void* d_out, int out_size) {
    const float* x   = (const float*)d_in[0];
    const int*   ei  = (const int*)d_in[1];
    const float* ew  = (const float*)d_in[3];
    const float* aew = (const float*)d_in[4];
    const float* aeb = (const float*)d_in[5];
    const float* W1  = (const float*)d_in[6];
    const float* b1  = (const float*)d_in[7];
    const float* g1  = (const float*)d_in[8];
    const float* be1 = (const float*)d_in[9];
    const float* W2  = (const float*)d_in[10];
    const float* b2  = (const float*)d_in[11];
    const float* go  = (const float*)d_in[12];
    const float* beo = (const float*)d_in[13];
    float* h = (float*)d_out;

    const int GB = (NN + 127) / 128;   // 391

    k_init<<<(NN + 255) / 256, 256>>>();
    k_hist<<<(EE + 255) / 256, 256>>>(ei);
    k_scanA<<<NG, GROUP>>>();
    // atom encoder as 4th launch (independent of scan chain; ncu captures #4)
    k_gemm<0, 0, 0, 0><<<GB, 512>>>(
        x, aew, aeb, h, nullptr, nullptr, 0, 0, NN);
    k_scanB<<<1, 128>>>();
    k_scanC<<<NG, GROUP>>>();
    k_fill<<<(EE + 255) / 256, 256>>>(ei, ew);

    for (int l = 0; l < LL; l++) {
        int sIn = 2 * l, sOut = 2 * l + 1;
        k_agg<<<(NN * 32 + 255) / 256, 256>>>(h);                    // -> bufA
        k_gemm<1, 0, 1, 2><<<GB, 512>>>(                             // bufA -> bufB, stats->sIn
            nullptr, W1 + l * EMBD * EMBD, b1 + l * EMBD, nullptr,
            nullptr, nullptr, 0, sIn, NN);
        k_gemm<1, 1, 2, 1><<<GB, 512>>>(                             // bufB -> bufA, BN(sIn), stats->sOut
            nullptr, W2 + l * EMBD * EMBD, b2 + l * EMBD, nullptr,
            g1 + l * EMBD, be1 + l * EMBD, sIn, sOut, NN);
        k_resid<<<(NN * EMBD / 4 + 255) / 256, 256>>>(               // h += relu(BN(bufA))
            h, go + l * EMBD, beo + l * EMBD, sOut);
    }
}

// round 8
// speedup vs baseline: 1.5137x; 1.5137x over previous
#include <cuda_runtime.h>

#define NN 50000
#define EE 800000
#define EMBD 64
#define LL 4
#define BN_EPS 1e-5f
#define GROUP 512
#define NG ((NN + GROUP - 1) / GROUP)   // 98

// ---------------- scratch (device globals; no allocation allowed) ----------
__device__ __align__(256) float g_bufA[NN * EMBD];   // agg output / t2
__device__ __align__(256) float g_bufB[NN * EMBD];   // t (gemm1 out)
__device__ int   g_off[NN + 1];
__device__ int   g_cur[NN];
__device__ int2  g_edge[EE];            // packed (src, weight-bits)
__device__ int   g_part[NG];
__device__ float g_sumL[8][64];         // per-BN stat slots (4 layers x {inner,outer})
__device__ float g_sqL[8][64];

// ---------------- init: zero counters + all stat slots ---------------------
__global__ void k_init() {
    int i = blockIdx.x * blockDim.x + threadIdx.x;
    if (i < NN) g_cur[i] = 0;
    if (i < 8 * 64) { (&g_sumL[0][0])[i] = 0.f; (&g_sqL[0][0])[i] = 0.f; }
}

__global__ void k_hist(const int* __restrict__ ei) {
    int e = blockIdx.x * blockDim.x + threadIdx.x;
    if (e < EE) atomicAdd(&g_cur[ei[EE + e]], 1);
}

// ---------------- 3-phase exclusive scan over g_cur -> g_off ---------------
__global__ void k_scanA() {
    __shared__ int s_warp[32];
    int tid = threadIdx.x, lane = tid & 31, wid = tid >> 5;
    int i = blockIdx.x * GROUP + tid;
    int d = (i < NN) ? g_cur[i] : 0;
    int v = d;
    #pragma unroll
    for (int o = 1; o < 32; o <<= 1) {
        int t = __shfl_up_sync(0xffffffffu, v, o);
        if (lane >= o) v += t;
    }
    if (lane == 31) s_warp[wid] = v;
    __syncthreads();
    if (wid == 0) {
        int w = (lane < 16) ? s_warp[lane] : 0;
        #pragma unroll
        for (int o = 1; o < 32; o <<= 1) {
            int t = __shfl_up_sync(0xffffffffu, w, o);
            if (lane >= o) w += t;
        }
        if (lane < 16) s_warp[lane] = w;
    }
    __syncthreads();
    int excl = (wid ? s_warp[wid - 1] : 0) + v - d;
    if (i < NN) g_off[i] = excl;
    if (tid == 0) g_part[blockIdx.x] = s_warp[15];   // block total
}

// parallel scan over NG (=98) partials, one 128-thread block
__global__ void k_scanB() {
    __shared__ int wtot[4];
    int tid = threadIdx.x, lane = tid & 31, wid = tid >> 5;
    int d = (tid < NG) ? g_part[tid] : 0;
    int v = d;
    #pragma unroll
    for (int o = 1; o < 32; o <<= 1) {
        int t = __shfl_up_sync(0xffffffffu, v, o);
        if (lane >= o) v += t;
    }
    if (lane == 31) wtot[wid] = v;
    __syncthreads();
    int add = 0;
    #pragma unroll
    for (int w = 0; w < 4; w++) add += (w < wid) ? wtot[w] : 0;
    if (tid < NG) g_part[tid] = add + v - d;
}

__global__ void k_scanC() {
    int i = blockIdx.x * GROUP + threadIdx.x;
    if (i < NN) {
        int o = g_off[i] + g_part[blockIdx.x];
        g_off[i] = o;
        g_cur[i] = o;
    }
    if (i == 0) g_off[NN] = EE;
}

__global__ void k_fill(const int* __restrict__ ei, const float* __restrict__ ew) {
    int e = blockIdx.x * blockDim.x + threadIdx.x;
    if (e < EE) {
        int d = ei[EE + e];
        int p = atomicAdd(&g_cur[d], 1);
        g_edge[p] = make_int2(ei[e], __float_as_int(ew[e]));
    }
}

// ---------------- aggregation: warp per node, no atomics, MLP=4 ------------
__global__ void k_agg(const float* __restrict__ h) {
    int gw   = (blockIdx.x * blockDim.x + threadIdx.x) >> 5;
    int lane = threadIdx.x & 31;
    if (gw >= NN) return;
    int beg = g_off[gw], end = g_off[gw + 1];
    const float2* __restrict__ h2 = (const float2*)h;
    float2 acc = h2[gw * 32 + lane];            // self term: agg + h
    int i = beg;
    for (; i + 4 <= end; i += 4) {
        int2 e0 = __ldg(&g_edge[i]);
        int2 e1 = __ldg(&g_edge[i + 1]);
        int2 e2 = __ldg(&g_edge[i + 2]);
        int2 e3 = __ldg(&g_edge[i + 3]);
        float2 v0 = h2[e0.x * 32 + lane];
        float2 v1 = h2[e1.x * 32 + lane];
        float2 v2 = h2[e2.x * 32 + lane];
        float2 v3 = h2[e3.x * 32 + lane];
        float w0 = __int_as_float(e0.y), w1 = __int_as_float(e1.y);
        float w2 = __int_as_float(e2.y), w3 = __int_as_float(e3.y);
        acc.x = fmaf(w0, v0.x, acc.x);  acc.y = fmaf(w0, v0.y, acc.y);
        acc.x = fmaf(w1, v1.x, acc.x);  acc.y = fmaf(w1, v1.y, acc.y);
        acc.x = fmaf(w2, v2.x, acc.x);  acc.y = fmaf(w2, v2.y, acc.y);
        acc.x = fmaf(w3, v3.x, acc.x);  acc.y = fmaf(w3, v3.y, acc.y);
    }
    for (; i < end; i++) {
        int2 e0 = __ldg(&g_edge[i]);
        float2 v0 = h2[e0.x * 32 + lane];
        float w0 = __int_as_float(e0.y);
        acc.x = fmaf(w0, v0.x, acc.x);
        acc.y = fmaf(w0, v0.y, acc.y);
    }
    ((float2*)g_bufA)[gw * 32 + lane] = acc;
}

// ----- 64x64 GEMM: 256 thr, 8x4 register tile/thread, f32x2, k-major X -----
// STATS: accumulate per-feature sum & sumsq of Y into slotOut
// TRANS: x -> relu(x*scale + shift) applied ONCE at staging time
// SRC/DST: 0 = use pointer arg, 1 = g_bufA, 2 = g_bufB
#define XPAD 132
template <int STATS, int TRANS, int SRC, int DST>
__global__ void __launch_bounds__(256, 3) k_gemm(
    const float* __restrict__ Xarg, const float* __restrict__ W,
    const float* __restrict__ bias, float* __restrict__ Yarg,
    const float* __restrict__ gma, const float* __restrict__ bta,
    int slotIn, int slotOut, int n)
{
    const float* X = (SRC == 1) ? g_bufA : (SRC == 2) ? g_bufB : Xarg;
    float*       Y = (DST == 1) ? g_bufA : (DST == 2) ? g_bufB : Yarg;

    __shared__ float4 Ws4[64 * 16];       // 16 KB, idx = k*16 + col4
    __shared__ float  Xt[2][16 * XPAD];   // 16.9 KB, k-major quarters, dbl-buf
    __shared__ float  Bs[64];
    __shared__ float  Ss[64];
    __shared__ float  Hs[64];
    __shared__ float  Rs[8 * 128];        // 4 KB: per-warp 64 sums + 64 sqs

    int tid  = threadIdx.x;
    int tx   = tid & 15;                  // col group: cols tx*4 .. tx*4+3
    int ty   = tid >> 4;                  // row group: rows ty*8 .. ty*8+7
    int base = blockIdx.x * 128;

    for (int i = tid; i < 64 * 16; i += 256) Ws4[i] = ((const float4*)W)[i];
    if (tid < 64) {
        Bs[tid] = bias[tid];
        if (TRANS) {
            float mean = g_sumL[slotIn][tid] * (1.f / NN);
            float var  = g_sqL[slotIn][tid] * (1.f / NN) - mean * mean;
            float rs   = rsqrtf(var + BN_EPS);
            float sc   = rs * gma[tid];
            Ss[tid] = sc;
            Hs[tid] = bta[tid] - mean * sc;
        }
    }

    // staging: quarter = 128 rows x 16 k = 512 float4; 2 float4 per thread
    int prow0 = tid >> 2, pc40 = tid & 3;            // u=0
    int prow1 = (tid + 256) >> 2, pc41 = tid & 3;    // u=1
    float4 pre0, pre1;
    auto loadQ = [&](int q) {
        pre0 = make_float4(0.f, 0.f, 0.f, 0.f);
        pre1 = make_float4(0.f, 0.f, 0.f, 0.f);
        if (base + prow0 < n) pre0 = ((const float4*)X)[(base + prow0) * 16 + q * 4 + pc40];
        if (base + prow1 < n) pre1 = ((const float4*)X)[(base + prow1) * 16 + q * 4 + pc41];
    };
    auto storeQ = [&](int b, int q) {
        float v0[4] = { pre0.x, pre0.y, pre0.z, pre0.w };
        float v1[4] = { pre1.x, pre1.y, pre1.z, pre1.w };
        #pragma unroll
        for (int i = 0; i < 4; i++) {
            int kl0 = pc40 * 4 + i, kl1 = pc41 * 4 + i;
            float a = v0[i], c = v1[i];
            if (TRANS) {
                a = fmaxf(fmaf(a, Ss[q * 16 + kl0], Hs[q * 16 + kl0]), 0.f);
                c = fmaxf(fmaf(c, Ss[q * 16 + kl1], Hs[q * 16 + kl1]), 0.f);
            }
            Xt[b][kl0 * XPAD + prow0] = a;
            Xt[b][kl1 * XPAD + prow1] = c;
        }
    };

    // 16 packed f32x2 accumulators: acc2[row-pair][col] (rows 2p,2p+1; col tx*4+c)
    unsigned long long acc2[4][4];
    #pragma unroll
    for (int p = 0; p < 4; p++)
        #pragma unroll
        for (int c = 0; c < 4; c++) acc2[p][c] = 0ull;

    loadQ(0);
    __syncthreads();            // Ss/Hs visible before TRANS staging
    storeQ(0, 0);
    __syncthreads();

    #pragma unroll
    for (int q = 0; q < 4; q++) {
        if (q < 3) loadQ(q + 1);                  // LDG in flight during compute
        const float* xp = Xt[q & 1];
        #pragma unroll
        for (int k = 0; k < 16; k++) {
            // rows as packed f32x2 directly from smem (no repacking)
            ulonglong2 xa = *(const ulonglong2*)&xp[k * XPAD + ty * 8];
            ulonglong2 xb = *(const ulonglong2*)&xp[k * XPAD + ty * 8 + 4];
            float4 wv = Ws4[(q * 16 + k) * 16 + tx];
            unsigned long long wd[4];
            asm("mov.b64 %0, {%1, %1};" : "=l"(wd[0]) : "r"(__float_as_uint(wv.x)));
            asm("mov.b64 %0, {%1, %1};" : "=l"(wd[1]) : "r"(__float_as_uint(wv.y)));
            asm("mov.b64 %0, {%1, %1};" : "=l"(wd[2]) : "r"(__float_as_uint(wv.z)));
            asm("mov.b64 %0, {%1, %1};" : "=l"(wd[3]) : "r"(__float_as_uint(wv.w)));
            #pragma unroll
            for (int c = 0; c < 4; c++) {
                asm("fma.rn.f32x2 %0, %1, %2, %0;" : "+l"(acc2[0][c]) : "l"(xa.x), "l"(wd[c]));
                asm("fma.rn.f32x2 %0, %1, %2, %0;" : "+l"(acc2[1][c]) : "l"(xa.y), "l"(wd[c]));
                asm("fma.rn.f32x2 %0, %1, %2, %0;" : "+l"(acc2[2][c]) : "l"(xb.x), "l"(wd[c]));
                asm("fma.rn.f32x2 %0, %1, %2, %0;" : "+l"(acc2[3][c]) : "l"(xb.y), "l"(wd[c]));
            }
        }
        if (q < 3) {
            storeQ((q + 1) & 1, q + 1);           // other buffer: safe pre-sync
            __syncthreads();
        }
    }

    // epilogue: bias, store, per-col stats (valid rows only)
    float4 b4 = ((const float4*)Bs)[tx];
    float ssum[4] = {0.f, 0.f, 0.f, 0.f};
    float ssq[4]  = {0.f, 0.f, 0.f, 0.f};
    #pragma unroll
    for (int p = 0; p < 4; p++) {
        #pragma unroll
        for (int hh = 0; hh < 2; hh++) {
            int r = 2 * p + hh;
            int grow = base + ty * 8 + r;
            float4 v;
            v.x = __uint_as_float(hh ? (unsigned)(acc2[p][0] >> 32) : (unsigned)acc2[p][0]);
            v.y = __uint_as_float(hh ? (unsigned)(acc2[p][1] >> 32) : (unsigned)acc2[p][1]);
            v.z = __uint_as_float(hh ? (unsigned)(acc2[p][2] >> 32) : (unsigned)acc2[p][2]);
            v.w = __uint_as_float(hh ? (unsigned)(acc2[p][3] >> 32) : (unsigned)acc2[p][3]);
            v.x += b4.x; v.y += b4.y; v.z += b4.z; v.w += b4.w;
            if (grow < n) {
                ((float4*)Y)[grow * 16 + tx] = v;
                if (STATS) {
                    ssum[0] += v.x; ssq[0] += v.x * v.x;
                    ssum[1] += v.y; ssq[1] += v.y * v.y;
                    ssum[2] += v.z; ssq[2] += v.z * v.z;
                    ssum[3] += v.w; ssq[3] += v.w * v.w;
                }
            }
        }
    }

    if (STATS) {
        int lane = tid & 31, wid = tid >> 5;
        #pragma unroll
        for (int c = 0; c < 4; c++) {
            float s = ssum[c] + __shfl_down_sync(0xffffffffu, ssum[c], 16);
            float q = ssq[c]  + __shfl_down_sync(0xffffffffu, ssq[c], 16);
            if (lane < 16) {
                Rs[wid * 128 + tx * 4 + c]      = s;
                Rs[wid * 128 + 64 + tx * 4 + c] = q;
            }
        }
        __syncthreads();
        if (tid < 128) {
            int f = tid & 63, w = tid >> 6;       // w=0: sum, w=1: sq
            float t = 0.f;
            #pragma unroll
            for (int wi = 0; wi < 8; wi++) t += Rs[wi * 128 + w * 64 + f];
            atomicAdd(w ? &g_sqL[slotOut][f] : &g_sumL[slotOut][f], t);
        }
    }
}

// ---------------- outer BN apply + ReLU + residual (t2 = g_bufA) -----------
__global__ void __launch_bounds__(256) k_resid(
    float* __restrict__ h, const float* __restrict__ gma,
    const float* __restrict__ bta, int slot)
{
    __shared__ float Ss[64];
    __shared__ float Hs[64];
    int tid = threadIdx.x;
    if (tid < 64) {
        float mean = g_sumL[slot][tid] * (1.f / NN);
        float var  = g_sqL[slot][tid] * (1.f / NN) - mean * mean;
        float rs   = rsqrtf(var + BN_EPS);
        float sc   = rs * gma[tid];
        Ss[tid] = sc;
        Hs[tid] = bta[tid] - mean * sc;
    }
    __syncthreads();
    int i = blockIdx.x * blockDim.x + tid;
    if (i < NN * EMBD / 4) {
        int fb = (i & 15) * 4;
        float4 v  = ((const float4*)g_bufA)[i];
        float4 hh = ((const float4*)h)[i];
        v.x = fmaxf(fmaf(v.x, Ss[fb + 0], Hs[fb + 0]), 0.f) + hh.x;
        v.y = fmaxf(fmaf(v.y, Ss[fb + 1], Hs[fb + 1]), 0.f) + hh.y;
        v.z = fmaxf(fmaf(v.z, Ss[fb + 2], Hs[fb + 2]), 0.f) + hh.z;
        v.w = fmaxf(fmaf(v.w, Ss[fb + 3], Hs[fb + 3]), 0.f) + hh.w;
        ((float4*)h)[i] = v;
    }
}

// ---------------- launch ----------------------------------------------------
extern "C" void kernel_launch(void* const* d_in, const int* in_sizes, int n_in,
                              void* d_out, int out_size) {
    const float* x   = (const float*)d_in[0];
    const int*   ei  = (const int*)d_in[1];
    const float* ew  = (const float*)d_in[3];
    const float* aew = (const float*)d_in[4];
    const float* aeb = (const float*)d_in[5];
    const float* W1  = (const float*)d_in[6];
    const float* b1  = (const float*)d_in[7];
    const float* g1  = (const float*)d_in[8];
    const float* be1 = (const float*)d_in[9];
    const float* W2  = (const float*)d_in[10];
    const float* b2  = (const float*)d_in[11];
    const float* go  = (const float*)d_in[12];
    const float* beo = (const float*)d_in[13];
    float* h = (float*)d_out;

    const int GB = (NN + 127) / 128;   // 391

    k_init<<<(NN + 255) / 256, 256>>>();
    k_hist<<<(EE + 255) / 256, 256>>>(ei);
    k_scanA<<<NG, GROUP>>>();
    // atom encoder as 4th launch (independent of scan chain; ncu captures #4)
    k_gemm<0, 0, 0, 0><<<GB, 256>>>(
        x, aew, aeb, h, nullptr, nullptr, 0, 0, NN);
    k_scanB<<<1, 128>>>();
    k_scanC<<<NG, GROUP>>>();
    k_fill<<<(EE + 255) / 256, 256>>>(ei, ew);

    for (int l = 0; l < LL; l++) {
        int sIn = 2 * l, sOut = 2 * l + 1;
        k_agg<<<(NN * 32 + 255) / 256, 256>>>(h);                    // -> bufA
        k_gemm<1, 0, 1, 2><<<GB, 256>>>(                             // bufA -> bufB, stats->sIn
            nullptr, W1 + l * EMBD * EMBD, b1 + l * EMBD, nullptr,
            nullptr, nullptr, 0, sIn, NN);
        k_gemm<1, 1, 2, 1><<<GB, 256>>>(                             // bufB -> bufA, BN(sIn), stats->sOut
            nullptr, W2 + l * EMBD * EMBD, b2 + l * EMBD, nullptr,
            g1 + l * EMBD, be1 + l * EMBD, sIn, sOut, NN);
        k_resid<<<(NN * EMBD / 4 + 255) / 256, 256>>>(               // h += relu(BN(bufA))
            h, go + l * EMBD, beo + l * EMBD, sOut);
    }
}